// round 14
// baseline (speedup 1.0000x reference)
#include <cuda_runtime.h>
#include <math.h>

#define BB 256
#define TT 512
#define II 128
#define HH 256
#define H2 512
#define H3 768
#define SMS 148
#define GRID 148
#define NTHR 256
#define GSTRIDE (GRID * NTHR)

typedef unsigned long long ull;

// BK=16 staging geometry
#define A_PITCH 34                 // ull per k-row (32 row-pairs + 2 pad)
#define W_PITCH 132                // f32 per k-row (128 cols + 4 pad)
#define ABUF (16 * A_PITCH)
#define WBUF (16 * W_PITCH)

enum { EPI_RAW = 0, EPI_TANH = 2 };

// ---------------- persistent device scratch (no allocations) ----------------
__device__ float g_W1t[H2 * H2];     // transposed: Wt[k][n] = W[n][k]
__device__ float g_W2t[H2 * H2];
__device__ float g_W3t[H2 * H2];
__device__ float g_WihT[HH * H3];
__device__ float g_WhhT[HH * H3];
__device__ float g_WcinT[II * HH];

__device__ float g_com[BB][H2];      // [c | c_in_t]
__device__ float g_a1p[4][BB][H2];   // MLP K-split-4 partials
__device__ float g_a2p[4][BB][H2];
__device__ float g_a3p[4][BB][H2];
__device__ float g_gip[2][BB][H3];   // gate K-split-2 partials (no bias)
__device__ float g_ghp[2][BB][H3];
__device__ float g_c[BB][HH];
__device__ float g_h[BB][HH];
__device__ float g_n[BB];

// ---------------- hierarchical barrier (monotonic, replay-safe) ----------------
__device__ unsigned g_cntG[32 * 32];
__device__ volatile unsigned g_genG;
__device__ unsigned g_epochG;

__device__ __forceinline__ void barrier_G(unsigned k)
{
    __syncthreads();
    if (threadIdx.x == 0) {
        __threadfence();
        atomicAdd(&g_cntG[(blockIdx.x & 31) << 5], 1u);
        if (blockIdx.x == 0) {
            unsigned long long need = (unsigned long long)k * GRID;
            for (;;) {
                unsigned long long s = 0;
#pragma unroll
                for (int i = 0; i < 32; i++)
                    s += ((volatile unsigned*)g_cntG)[i << 5];
                if (s >= need) break;
                __nanosleep(64);
            }
            __threadfence();
            g_genG = k;
        } else {
            while (g_genG < k) __nanosleep(96);
        }
        __threadfence();
    }
    __syncthreads();
}

__device__ __forceinline__ float sigf(float x) { return 1.f / (1.f + expf(-x)); }

__device__ __forceinline__ ull pack2(float x, float y) {
    ull r; asm("mov.b64 %0,{%1,%2};" : "=l"(r) : "f"(x), "f"(y)); return r;
}
__device__ __forceinline__ void unpack2(ull v, float& x, float& y) {
    asm("mov.b64 {%0,%1},%2;" : "=f"(x), "=f"(y) : "l"(v));
}
__device__ __forceinline__ void fma2(ull& d, ull a, ull b) {
    asm("fma.rn.f32x2 %0, %1, %2, %0;" : "+l"(d) : "l"(a), "l"(b));
}

// -------------------------------------------------------------------------
// 64x128 output tile, K=128 (8 k-tiles of 16), 256 threads, per-thread 8x4.
// Compute: warp handles rows 8*warp..8*warp+7 -> A reads are warp-uniform
// (broadcast, ~free crossbar); W read = 1 LDS.128/lane/kk; 16 FFMA2/kk.
// Per SMSP-kk: 2 warps x 16 FFMA2 x rt2 = 64 cyc -> fma-pipe-saturating.
// NSRC=4: A = relu(sum of 4 partials + kb) folded into the prefetch.
// -------------------------------------------------------------------------
template<int EPI, int NSRC>
__device__ __noinline__ void gemm8x4(
    const float* __restrict__ A0, size_t srcStride, const float* __restrict__ kb,
    int lda, int koff,
    const float* __restrict__ Wt, int ldw,
    const float* __restrict__ bias,
    float* __restrict__ C, int ldc,
    int rowBase, int colBase,
    ull* __restrict__ As, float* __restrict__ Ws)
{
    const int tid = threadIdx.x;
    const int tx  = tid & 31;       // col group: cols 4tx..4tx+3
    const int ty  = tid >> 5;       // warp: rows 8ty..8ty+7 (pairs 4ty..4ty+3)
    const int p   = tid >> 3;       // A loader: pair 0..31 (rows 2p, 2p+1)
    const int kq  = tid & 7;        // A loader: k-pair (k = 2kq, 2kq+1)
    const int wk  = tid >> 4;       // W loader: k row 0..15
    const int wc  = tid & 15;       // W loader: col oct (8 floats)

    ull acc[4][4];
#pragma unroll
    for (int i = 0; i < 4; i++)
#pragma unroll
        for (int j = 0; j < 4; j++) acc[i][j] = 0;

    float2 x0, x1;
    float4 wv0, wv1;

#define LOAD_T(kt)                                                             \
    {                                                                          \
        int kg = koff + (kt) * 16 + 2 * kq;                                    \
        const float* ap = A0 + (size_t)(rowBase + 2 * p) * lda + kg;           \
        x0 = *(const float2*)ap;                                               \
        x1 = *(const float2*)(ap + lda);                                       \
        if (NSRC == 4) {                                                       \
            _Pragma("unroll")                                                  \
            for (int s = 1; s < 4; s++) {                                      \
                const float* bp = ap + s * srcStride;                          \
                float2 u0 = *(const float2*)bp;                                \
                float2 u1 = *(const float2*)(bp + lda);                        \
                x0.x += u0.x; x0.y += u0.y;                                    \
                x1.x += u1.x; x1.y += u1.y;                                    \
            }                                                                  \
            float2 bb = *(const float2*)(kb + kg);                             \
            x0.x = fmaxf(x0.x + bb.x, 0.f);                                    \
            x0.y = fmaxf(x0.y + bb.y, 0.f);                                    \
            x1.x = fmaxf(x1.x + bb.x, 0.f);                                    \
            x1.y = fmaxf(x1.y + bb.y, 0.f);                                    \
        }                                                                      \
        const float* wp = Wt + (size_t)(koff + (kt) * 16 + wk) * ldw           \
                          + colBase + 8 * wc;                                  \
        wv0 = *(const float4*)wp;                                              \
        wv1 = *(const float4*)(wp + 4);                                        \
    }

#define STORE_T(bi)                                                            \
    {                                                                          \
        ull* as = As + (bi) * ABUF;                                            \
        as[(2 * kq + 0) * A_PITCH + p] = pack2(x0.x, x1.x);                    \
        as[(2 * kq + 1) * A_PITCH + p] = pack2(x0.y, x1.y);                    \
        float* ws = Ws + (bi) * WBUF;                                          \
        *(float4*)(ws + wk * W_PITCH + 8 * wc)     = wv0;                      \
        *(float4*)(ws + wk * W_PITCH + 8 * wc + 4) = wv1;                      \
    }

    LOAD_T(0);
    STORE_T(0);
    __syncthreads();

#pragma unroll 1
    for (int kt = 0; kt < 8; kt++) {
        if (kt < 7) LOAD_T(kt + 1);
        {
            const ull*   as = As + (kt & 1) * ABUF;
            const float* ws = Ws + (kt & 1) * WBUF;
#pragma unroll
            for (int kk = 0; kk < 16; kk++) {
                ulonglong2 aA = *(const ulonglong2*)&as[kk * A_PITCH + 4 * ty];
                ulonglong2 aB = *(const ulonglong2*)&as[kk * A_PITCH + 4 * ty + 2];
                float4 wv = *(const float4*)&ws[kk * W_PITCH + 4 * tx];
                ull w0 = pack2(wv.x, wv.x), w1 = pack2(wv.y, wv.y);
                ull w2 = pack2(wv.z, wv.z), w3 = pack2(wv.w, wv.w);
                fma2(acc[0][0], aA.x, w0); fma2(acc[0][1], aA.x, w1);
                fma2(acc[0][2], aA.x, w2); fma2(acc[0][3], aA.x, w3);
                fma2(acc[1][0], aA.y, w0); fma2(acc[1][1], aA.y, w1);
                fma2(acc[1][2], aA.y, w2); fma2(acc[1][3], aA.y, w3);
                fma2(acc[2][0], aB.x, w0); fma2(acc[2][1], aB.x, w1);
                fma2(acc[2][2], aB.x, w2); fma2(acc[2][3], aB.x, w3);
                fma2(acc[3][0], aB.y, w0); fma2(acc[3][1], aB.y, w1);
                fma2(acc[3][2], aB.y, w2); fma2(acc[3][3], aB.y, w3);
            }
        }
        if (kt < 7) STORE_T((kt + 1) & 1);
        __syncthreads();
    }
#undef LOAD_T
#undef STORE_T

    // epilogue: acc[pp][c] -> rows rowBase+8ty+2pp (+1), cols colBase+4tx..+3
    float4 bv;
    if (EPI == EPI_TANH) bv = *(const float4*)(bias + colBase + 4 * tx);
#pragma unroll
    for (int pp = 0; pp < 4; pp++) {
        float e0, e1, e2, e3, o0, o1, o2, o3;
        unpack2(acc[pp][0], e0, o0);
        unpack2(acc[pp][1], e1, o1);
        unpack2(acc[pp][2], e2, o2);
        unpack2(acc[pp][3], e3, o3);
        float4 ev = make_float4(e0, e1, e2, e3);
        float4 ov = make_float4(o0, o1, o2, o3);
        if (EPI == EPI_TANH) {
            ev.x = tanhf(ev.x + bv.x); ev.y = tanhf(ev.y + bv.y);
            ev.z = tanhf(ev.z + bv.z); ev.w = tanhf(ev.w + bv.w);
            ov.x = tanhf(ov.x + bv.x); ov.y = tanhf(ov.y + bv.y);
            ov.z = tanhf(ov.z + bv.z); ov.w = tanhf(ov.w + bv.w);
        }
        float* c0 = C + (size_t)(rowBase + 8 * ty + 2 * pp) * ldc + colBase + 4 * tx;
        *(float4*)c0         = ev;
        *(float4*)(c0 + ldc) = ov;
    }
}

// MLP job j in [0,64): rt(0..3) x ct(0..3) x kh(0..3); 64x128 tile, K=128
__device__ __forceinline__ void mlp_job(int ph, int j, const float* b1,
                                        const float* b2, ull* As, float* Ws)
{
    int rt = j >> 4, ct = (j >> 2) & 3, kh = j & 3;
    int rb = rt * 64, cb = ct * 128, ko = kh * 128;
    if (ph == 0)
        gemm8x4<EPI_RAW, 1>(&g_com[0][0], 0, 0, H2, ko, g_W1t, H2, 0,
                            &g_a1p[kh][0][0], H2, rb, cb, As, Ws);
    else if (ph == 1)
        gemm8x4<EPI_RAW, 4>(&g_a1p[0][0][0], (size_t)BB * H2, b1, H2, ko,
                            g_W2t, H2, 0, &g_a2p[kh][0][0], H2, rb, cb, As, Ws);
    else
        gemm8x4<EPI_RAW, 4>(&g_a2p[0][0][0], (size_t)BB * H2, b2, H2, ko,
                            g_W3t, H2, 0, &g_a3p[kh][0][0], H2, rb, cb, As, Ws);
}

// gate job g in [0,96): g<48 gi else gh; q -> rt(0..3) x ct(0..5) x kh(0..1)
__device__ __forceinline__ void gate_job(int g, ull* As, float* Ws)
{
    bool is_gi = g < 48;
    int q = is_gi ? g : g - 48;
    int rt = q / 12, rem = q % 12, ct = rem >> 1, kh = rem & 1;
    int rb = rt * 64, cb = ct * 128, ko = kh * 128;
    if (is_gi)
        gemm8x4<EPI_RAW, 1>(&g_c[0][0], 0, 0, HH, ko, g_WihT, H3, 0,
                            &g_gip[kh][0][0], H3, rb, cb, As, Ws);
    else
        gemm8x4<EPI_RAW, 1>(&g_h[0][0], 0, 0, HH, ko, g_WhhT, H3, 0,
                            &g_ghp[kh][0][0], H3, rb, cb, As, Ws);
}

// =========================== persistent megakernel ===========================
__global__ void __launch_bounds__(NTHR, 1)
rnn_persistent(const float* __restrict__ input, const float* __restrict__ noise,
               const float* __restrict__ Wcin, const float* __restrict__ bcin,
               const float* __restrict__ W1, const float* __restrict__ b1,
               const float* __restrict__ W2, const float* __restrict__ b2,
               const float* __restrict__ W3, const float* __restrict__ b3,
               const float* __restrict__ W4, const float* __restrict__ b4,
               const float* __restrict__ Wih, const float* __restrict__ Whh,
               const float* __restrict__ bih, const float* __restrict__ bhh,
               float* __restrict__ outC, float* __restrict__ outH,
               float* __restrict__ outF)
{
    __shared__ __align__(16) ull   sAs[2 * ABUF];
    __shared__ __align__(16) float sWs[2 * WBUF];
    __shared__ float su[16];

    const int bid = blockIdx.x;
    const int tid = threadIdx.x;
    const int gt  = bid * NTHR + tid;

    unsigned kG = g_epochG;

    // -------- weight transposes (once per launch) --------
    for (int i = gt; i < H2 * H2; i += GSTRIDE) {
        int k = i / H2, n = i % H2;
        g_W1t[i] = W1[(size_t)n * H2 + k];
        g_W2t[i] = W2[(size_t)n * H2 + k];
        g_W3t[i] = W3[(size_t)n * H2 + k];
    }
    for (int i = gt; i < HH * H3; i += GSTRIDE) {
        int k = i / H3, n = i % H3;
        g_WihT[i] = Wih[(size_t)n * HH + k];
        g_WhhT[i] = Whh[(size_t)n * HH + k];
    }
    for (int i = gt; i < II * HH; i += GSTRIDE) {
        int k = i / HH, n = i % HH;
        g_WcinT[i] = Wcin[(size_t)n * II + k];
    }
    barrier_G(++kG);

    // -------- prologue: c_in = tanh(x @ Wcin^T) -> c_concat (row = b*T+t) --------
    for (int j = bid; j < 4096; j += GRID) {
        int rt = j >> 1, ct = j & 1;
        gemm8x4<EPI_TANH, 1>(input, 0, 0, II, 0, g_WcinT, HH, bcin,
                             outC, HH, rt * 64, ct * 128, sAs, sWs);
    }
    barrier_G(++kG);

    // -------- init state --------
    for (int b = bid; b < BB; b += GRID) {
        g_c[b][tid] = 0.f;
        g_h[b][tid] = 0.f;
        g_com[b][tid] = 0.f;
        g_com[b][HH + tid] = outC[(size_t)b * TT * HH + tid];
        if (tid == 0) g_n[b] = 0.f;
    }
    barrier_G(++kG);

    // -------- recurrent loop --------
    for (int t = 0; t < TT; t++) {
        // ph0: a1 (64) + gates 0..83 -> exactly 148 jobs, 1 per SM
        if (bid < 64) mlp_job(0, bid, b1, b2, sAs, sWs);
        else          gate_job(bid - 64, sAs, sWs);
        barrier_G(++kG);
        // ph1: a2 (64) + gates 84..95
        if (bid < 64)      mlp_job(1, bid, b1, b2, sAs, sWs);
        else if (bid < 76) gate_job(84 + (bid - 64), sAs, sWs);
        barrier_G(++kG);
        // ph2: a3 (64)
        if (bid < 64) mlp_job(2, bid, b1, b2, sAs, sWs);
        barrier_G(++kG);

        // -------- phase U: two batches per CTA --------
        for (int rep = 0; rep < 2; rep++) {
            int b = bid + rep * GRID;
            if (b < BB) {
                float part = 0.f;
#pragma unroll
                for (int q = 0; q < 2; q++) {
                    int k = tid + q * NTHR;
                    float v = g_a3p[0][b][k] + g_a3p[1][b][k] + g_a3p[2][b][k]
                            + g_a3p[3][b][k] + b3[k];
                    part += fmaxf(v, 0.f) * W4[k];
                }
#pragma unroll
                for (int sh = 16; sh > 0; sh >>= 1)
                    part += __shfl_down_sync(0xffffffffu, part, sh);
                if ((tid & 31) == 0) su[tid >> 5] = part;
                __syncthreads();
                if (tid == 0) {
                    float logit = b4[0];
#pragma unroll
                    for (int w = 0; w < 8; w++) logit += su[w];
                    float u = noise[(size_t)t * BB + b];
                    float logistic = logf(u) - log1pf(-u);
                    float a = sigf((logit + logistic) * 10.f);   // / TEMP
                    float nold = g_n[b];
                    su[8] = a;
                    su[9] = nold;
                    g_n[b] = nold * (1.f - a) + 1.f;
                }
                __syncthreads();
                float alpha = su[8], nold = su[9];
                float nnew = nold * (1.f - alpha) + 1.f;
                int jj = tid;
                float c = g_c[b][jj], h = g_h[b][jj];
                float cin = outC[(size_t)b * TT * HH + (size_t)t * HH + jj];
                float gir = g_gip[0][b][jj] + g_gip[1][b][jj] + bih[jj];
                float ghr = g_ghp[0][b][jj] + g_ghp[1][b][jj] + bhh[jj];
                float giz = g_gip[0][b][HH + jj] + g_gip[1][b][HH + jj] + bih[HH + jj];
                float ghz = g_ghp[0][b][HH + jj] + g_ghp[1][b][HH + jj] + bhh[HH + jj];
                float gin = g_gip[0][b][2 * HH + jj] + g_gip[1][b][2 * HH + jj] + bih[2 * HH + jj];
                float ghn = g_ghp[0][b][2 * HH + jj] + g_ghp[1][b][2 * HH + jj] + bhh[2 * HH + jj];
                float r  = sigf(gir + ghr);
                float z  = sigf(giz + ghz);
                float ng = tanhf(gin + r * ghn);
                float hcand = (1.f - z) * ng + z * h;
                float hnew = h * (1.f - alpha) + alpha * hcand;
                float cnew = (c * nold * (1.f - alpha) + cin) / nnew;
                g_c[b][jj] = cnew;
                g_h[b][jj] = hnew;
                outH[(size_t)b * TT * HH + (size_t)t * HH + jj] = hnew;
                g_com[b][jj] = cnew;
                if (t + 1 < TT)
                    g_com[b][HH + jj] = outC[(size_t)b * TT * HH + (size_t)(t + 1) * HH + jj];
                __syncthreads();
            }
        }
        barrier_G(++kG);
    }

    // -------- epilogue: h_final = gru_cell(c_T, h_T) --------
    if (bid < 96) gate_job(bid, sAs, sWs);
    barrier_G(++kG);
    for (int b = bid; b < BB; b += GRID) {
        int jj = tid;
        float h = g_h[b][jj];
        float gir = g_gip[0][b][jj] + g_gip[1][b][jj] + bih[jj];
        float ghr = g_ghp[0][b][jj] + g_ghp[1][b][jj] + bhh[jj];
        float giz = g_gip[0][b][HH + jj] + g_gip[1][b][HH + jj] + bih[HH + jj];
        float ghz = g_ghp[0][b][HH + jj] + g_ghp[1][b][HH + jj] + bhh[HH + jj];
        float gin = g_gip[0][b][2 * HH + jj] + g_gip[1][b][2 * HH + jj] + bih[2 * HH + jj];
        float ghn = g_ghp[0][b][2 * HH + jj] + g_ghp[1][b][2 * HH + jj] + bhh[2 * HH + jj];
        float r  = sigf(gir + ghr);
        float z  = sigf(giz + ghz);
        float ng = tanhf(gin + r * ghn);
        outF[(size_t)b * HH + jj] = (1.f - z) * ng + z * h;
    }

    // persist episode base for the next launch / graph replay
    if (bid == 0 && tid == 0) g_epochG = kG;
}

extern "C" void kernel_launch(void* const* d_in, const int* in_sizes, int n_in,
                              void* d_out, int out_size)
{
    const float* input = (const float*)d_in[0];
    const float* noise = (const float*)d_in[1];
    const float* Wcin  = (const float*)d_in[2];
    const float* bcin  = (const float*)d_in[3];
    const float* W1    = (const float*)d_in[4];
    const float* b1    = (const float*)d_in[5];
    const float* W2    = (const float*)d_in[6];
    const float* b2    = (const float*)d_in[7];
    const float* W3    = (const float*)d_in[8];
    const float* b3    = (const float*)d_in[9];
    const float* W4    = (const float*)d_in[10];
    const float* b4    = (const float*)d_in[11];
    const float* Wih   = (const float*)d_in[12];
    const float* Whh   = (const float*)d_in[13];
    const float* bih   = (const float*)d_in[14];
    const float* bhh   = (const float*)d_in[15];

    float* outC = (float*)d_out;                   // c_concat [B,T,H]
    float* outH = outC + (size_t)BB * TT * HH;     // h_concat [B,T,H]
    float* outF = outH + (size_t)BB * TT * HH;     // h_final  [B,H]

    rnn_persistent<<<GRID, NTHR>>>(input, noise, Wcin, bcin, W1, b1, W2, b2,
                                   W3, b3, W4, b4, Wih, Whh, bih, bhh,
                                   outC, outH, outF);
}